// round 1
// baseline (speedup 1.0000x reference)
#include <cuda_runtime.h>
#include <cstdint>

// CausalRevIN: out = clip((x - mean)/std, -100, 100) with causal running
// mean = cumsum(x)/n, n = max(cumsum(1-mask),1),
// std = sqrt(cumsum(((x-mean)*(1-mask))^2)/n), std<=1e-5 -> 1.
//
// Shapes fixed by the problem: B=16, T=8192, C=128, all float32, C innermost.

namespace {
constexpr int Bn = 16;
constexpr int Tn = 8192;
constexpr int Cn = 128;

constexpr int C_SUB   = 2;              // channels per block
constexpr int THREADS = 256;
constexpr int TPC     = 128;            // threads per channel
constexpr int CHUNK   = Tn / TPC;       // 64 timesteps per thread
constexpr int PADC    = CHUNK + 1;      // 65: stride-65 => bank-conflict-free
constexpr int CH_STRIDE = TPC * PADC;   // 8320 floats per channel tile
constexpr int NMW     = Tn / 32;        // 256 bitmask words per channel

constexpr int SMEM_FLOATS = C_SUB * CH_STRIDE;                  // 16640
constexpr int SMEM_BYTES  = SMEM_FLOATS * 4                     // x tile 66560
                          + C_SUB * NMW * 4                     // nm bits 2048
                          + 3 * 8 * 4 + 32;                     // scan scratch
} // namespace

__device__ __forceinline__ float warp_incl_scan(float v, int lane) {
#pragma unroll
    for (int d = 1; d < 32; d <<= 1) {
        float u = __shfl_up_sync(0xffffffffu, v, d);
        if (lane >= d) v += u;
    }
    return v;
}

__global__ __launch_bounds__(THREADS, 3)
void crevin_kernel(const float* __restrict__ xg,
                   const float* __restrict__ mg,
                   float* __restrict__ og)
{
    extern __shared__ float smem[];
    float*    x_s  = smem;                                            // [C_SUB][CH_STRIDE]
    unsigned* nm_w = reinterpret_cast<unsigned*>(smem + SMEM_FLOATS); // [C_SUB][NMW]
    float*    wsx  = reinterpret_cast<float*>(nm_w + C_SUB * NMW);    // [8]
    float*    wsn  = wsx + 8;                                         // [8]
    float*    wsy  = wsn + 8;                                         // [8]

    const int tid  = threadIdx.x;
    const int lane = tid & 31;
    const int c    = tid >> 7;        // channel within block (0..1)
    const int j    = tid & 127;       // chunk index within channel (0..127)
    const int wid  = tid >> 5;        // warp id (0..7)
    const int wc   = wid & 3;         // warp within channel (0..3)

    const int b  = blockIdx.y;        // batch
    const int cg = blockIdx.x;        // channel-pair group (0..63)

    const float2* x2 = reinterpret_cast<const float2*>(xg);
    const float2* m2 = reinterpret_cast<const float2*>(mg);
    float2*       o2 = reinterpret_cast<float2*>(og);
    const size_t rowBase = (size_t)b * Tn * (Cn / 2) + cg;

    // ---- Phase 0: coalesced load; x -> padded SMEM tile, mask -> bit words ----
#pragma unroll 4
    for (int t = tid; t < Tn; t += THREADS) {
        const size_t gi = rowBase + (size_t)t * (Cn / 2);
        const float2 xv = x2[gi];
        const float2 mv = m2[gi];
        const int base  = (t >> 6) * PADC + (t & 63);
        x_s[base]             = xv.x;
        x_s[CH_STRIDE + base] = xv.y;
        // bit set where observed (mask == 0)
        const unsigned b0 = __ballot_sync(0xffffffffu, mv.x == 0.0f);
        const unsigned b1 = __ballot_sync(0xffffffffu, mv.y == 0.0f);
        if (lane == 0) {
            const int w = t >> 5;
            nm_w[w]       = b0;
            nm_w[NMW + w] = b1;
        }
    }
    __syncthreads();

    const int base     = c * CH_STRIDE + j * PADC;
    const unsigned w0  = nm_w[c * NMW + 2 * j];
    const unsigned w1  = nm_w[c * NMW + 2 * j + 1];

    // ---- Phase 1: per-chunk sums of x and nm ----
    float cx = 0.0f;
#pragma unroll 16
    for (int i = 0; i < CHUNK; i++) cx += x_s[base + i];
    float cn = (float)(__popc(w0) + __popc(w1));

    // exclusive prefix over the 128 chunks of this channel
    float ix  = warp_incl_scan(cx, lane);
    float in_ = warp_incl_scan(cn, lane);
    if (lane == 31) { wsx[wid] = ix; wsn[wid] = in_; }
    __syncthreads();
    float sx0 = ix  - cx;
    float sn0 = in_ - cn;
#pragma unroll
    for (int k = 0; k < 3; k++) {
        if (k < wc) { sx0 += wsx[(c << 2) + k]; sn0 += wsn[(c << 2) + k]; }
    }

    // ---- Phase 2: running mean, d = x - mean (stored in place), chunk sum of y ----
    float sx = sx0, sn = sn0, cy = 0.0f;
#pragma unroll 16
    for (int i = 0; i < CHUNK; i++) {
        const float xv = x_s[base + i];
        const unsigned word = (i < 32) ? w0 : w1;
        const float bf = (float)((word >> (i & 31)) & 1u);
        sx += xv;
        sn += bf;
        const float nd   = (sn == 0.0f) ? 1.0f : sn;
        const float mean = __fdividef(sx, nd);
        const float d    = xv - mean;
        const float db   = d * bf;
        cy = fmaf(db, db, cy);
        x_s[base + i] = d;
    }

    float iy = warp_incl_scan(cy, lane);
    if (lane == 31) wsy[wid] = iy;
    __syncthreads();
    float sy = iy - cy;
#pragma unroll
    for (int k = 0; k < 3; k++) {
        if (k < wc) sy += wsy[(c << 2) + k];
    }

    // ---- Phase 3: running variance, normalize + clamp (stored in place) ----
    float sn3 = sn0;
#pragma unroll 16
    for (int i = 0; i < CHUNK; i++) {
        const float d = x_s[base + i];
        const unsigned word = (i < 32) ? w0 : w1;
        const float bf = (float)((word >> (i & 31)) & 1u);
        sn3 += bf;
        const float db = d * bf;
        sy = fmaf(db, db, sy);
        const float nd  = (sn3 == 0.0f) ? 1.0f : sn3;
        const float var = __fdividef(sy, nd);
        // std > 1e-5  <=>  var > 1e-10 ; otherwise std := 1
        const float inv_std = (var > 1e-10f) ? rsqrtf(var) : 1.0f;
        float r = d * inv_std;
        r = fminf(100.0f, fmaxf(-100.0f, r));
        x_s[base + i] = r;
    }
    __syncthreads();

    // ---- Phase 4: coalesced store ----
#pragma unroll 4
    for (int t = tid; t < Tn; t += THREADS) {
        const int sb = (t >> 6) * PADC + (t & 63);
        float2 ov;
        ov.x = x_s[sb];
        ov.y = x_s[CH_STRIDE + sb];
        o2[rowBase + (size_t)t * (Cn / 2)] = ov;
    }
}

extern "C" void kernel_launch(void* const* d_in, const int* in_sizes, int n_in,
                              void* d_out, int out_size) {
    const float* x = (const float*)d_in[0];
    const float* m = (const float*)d_in[1];
    float*       o = (float*)d_out;

    cudaFuncSetAttribute(crevin_kernel,
                         cudaFuncAttributeMaxDynamicSharedMemorySize, SMEM_BYTES);

    dim3 grid(Cn / C_SUB, Bn);   // cg fastest-varying -> neighbor channel groups
                                 // of the same batch co-scheduled (L2 sector dedup)
    crevin_kernel<<<grid, THREADS, SMEM_BYTES>>>(x, m, o);
}

// round 2
// speedup vs baseline: 2.2084x; 2.2084x over previous
#include <cuda_runtime.h>
#include <cstdint>

// CausalRevIN, B=16, T=8192, C=128, f32, C innermost.
// out = clip((x - mean)/std, -100, 100), mean = cumsum(x)/n, n = max(cumsum(1-mask),1),
// std = sqrt(cumsum(((x-mean)*(1-mask))^2)/n); std<=1e-5 -> 1.
//
// Block = (b, 32-channel group, T-segment of 512). Warp lanes span the 32
// channels -> every global access is a single coalesced 128B line.
// Segments chain through L2-resident state (single-hop inclusive prefix):
//   chain A: (sum_x, sum_n) published after local phase-1 scan
//   chain B: sum_y published after phase 2
// Deterministic (fixed addition order), deadlock-free (deps point to lower bid).

namespace {
constexpr int Bn = 16;
constexpr int Tn = 8192;
constexpr int Cn = 128;

constexpr int CS      = 32;            // channels per block (warp-wide)
constexpr int LINKS   = 16;            // T segments / chain length
constexpr int TSEG    = Tn / LINKS;    // 512
constexpr int THREADS = 256;
constexpr int TPC     = THREADS / CS;  // 8 chunks per channel (= warp id)
constexpr int CHUNK   = TSEG / TPC;    // 64 timesteps per thread
constexpr int CH_STRIDE = TPC * (CHUNK + 1) + 1;  // 521 (odd mod 32 -> conflict-free)
constexpr int NCG     = Cn / CS;       // 4 channel groups

constexpr int SMEM_X      = CS * CH_STRIDE;       // 16672 floats
constexpr int SMEM_FLOATS = SMEM_X + 3 * THREADS; // + scan scratch
constexpr int SMEM_BYTES  = SMEM_FLOATS * 4;      // ~69.8 KB -> 3 blocks/SM

constexpr int NCHAIN = Bn * NCG * LINKS;          // 1024
constexpr int NSTATE = NCHAIN * CS;               // 32768 floats per array
} // namespace

__device__ float    g_sx[NSTATE];
__device__ float    g_sn[NSTATE];
__device__ float    g_sy[NSTATE];
__device__ unsigned g_flags[2 * NCHAIN];          // [phase A|B][b][cg][link]

__device__ __forceinline__ unsigned ld_acquire(const unsigned* p) {
    unsigned v;
    asm volatile("ld.acquire.gpu.global.u32 %0, [%1];" : "=r"(v) : "l"(p) : "memory");
    return v;
}
__device__ __forceinline__ void st_release(unsigned* p, unsigned v) {
    asm volatile("st.release.gpu.global.u32 [%0], %1;" :: "l"(p), "r"(v) : "memory");
}

__global__ __launch_bounds__(THREADS, 3)
void crevin_kernel(const float* __restrict__ xg,
                   const float* __restrict__ mg,
                   float* __restrict__ og)
{
    extern __shared__ float sm[];
    float* x_s  = sm;                 // [CS][CH_STRIDE], thread-private chunks
    float* sc_x = sm + SMEM_X;        // [TPC][CS] chunk sums
    float* sc_n = sc_x + THREADS;
    float* sc_y = sc_n + THREADS;

    const int tid  = threadIdx.x;
    const int c    = tid & 31;        // channel within group = lane
    const int j    = tid >> 5;        // chunk index = warp id (0..7)
    const int link = blockIdx.x;      // T segment (fastest-varying bid)
    const int cg   = blockIdx.y;
    const int b    = blockIdx.z;

    const size_t gbase = ((size_t)b * Tn + (size_t)link * TSEG + j * CHUNK) * Cn
                       + cg * CS + c;
    const int sbase = c * CH_STRIDE + j * (CHUNK + 1);

    // ---- load (coalesced 128B/warp) + fused phase 1 + mask bit-words ----
    float cx = 0.0f;
    unsigned w0 = 0u, w1 = 0u;
#pragma unroll 16
    for (int i = 0; i < CHUNK; i++) {
        const float xv = __ldcs(xg + gbase + (size_t)i * Cn);
        const float mv = __ldcs(mg + gbase + (size_t)i * Cn);
        x_s[sbase + i] = xv;
        cx += xv;
        const unsigned bit = (mv == 0.0f) ? 1u : 0u;   // 1 = observed
        if (i < 32) w0 |= bit << i; else w1 |= bit << (i - 32);
    }
    const float cn = (float)(__popc(w0) + __popc(w1));

    // ---- local exclusive scan over the 8 chunks of each channel ----
    sc_x[j * 32 + c] = cx;
    sc_n[j * 32 + c] = cn;
    __syncthreads();
    float px = 0.0f, pn = 0.0f;
    for (int k = 0; k < j; k++) {          // j is warp-uniform
        px += sc_x[k * 32 + c];
        pn += sc_n[k * 32 + c];
    }

    const int chain = (b * NCG + cg) * LINKS + link;
    const int sidx  = chain * CS + c;

    // ---- chain A: wait for predecessor's inclusive (sum_x, sum_n) ----
    float bx = 0.0f, bn = 0.0f;
    if (link > 0) {
        if (tid == 0) { while (ld_acquire(&g_flags[chain - 1]) == 0u) {} }
        __syncthreads();
        bx = __ldcg(&g_sx[sidx - CS]);
        bn = __ldcg(&g_sn[sidx - CS]);
    }
    const float sx0 = bx + px;
    const float sn0 = bn + pn;

    if (j == TPC - 1) {                    // publisher warp: inclusive totals
        g_sx[sidx] = sx0 + cx;
        g_sn[sidx] = sn0 + cn;
        __threadfence();
        __syncwarp();
        if (c == 0) st_release(&g_flags[chain], 1u);
    }

    // ---- phase 2: running mean, d = x - mean (in place), chunk sum of y ----
    float sx = sx0, sn = sn0, cy = 0.0f;
#pragma unroll 16
    for (int i = 0; i < CHUNK; i++) {
        const float xv = x_s[sbase + i];
        const float bf = (float)(((i < 32 ? (w0 >> i) : (w1 >> (i - 32))) & 1u));
        sx += xv;
        sn += bf;
        const float nd   = (sn == 0.0f) ? 1.0f : sn;
        const float mean = __fdividef(sx, nd);
        const float d    = xv - mean;
        x_s[sbase + i]   = d;
        const float db   = d * bf;
        cy = fmaf(db, db, cy);
    }

    sc_y[j * 32 + c] = cy;
    __syncthreads();
    float py = 0.0f;
    for (int k = 0; k < j; k++) py += sc_y[k * 32 + c];

    // ---- chain B: wait for predecessor's inclusive sum_y ----
    float by = 0.0f;
    if (link > 0) {
        if (tid == 0) { while (ld_acquire(&g_flags[NCHAIN + chain - 1]) == 0u) {} }
        __syncthreads();
        by = __ldcg(&g_sy[sidx - CS]);
    }
    float sy = by + py;

    if (j == TPC - 1) {
        g_sy[sidx] = sy + cy;
        __threadfence();
        __syncwarp();
        if (c == 0) st_release(&g_flags[NCHAIN + chain], 1u);
    }

    // ---- phase 3 fused with coalesced store ----
    float sn3 = sn0;
#pragma unroll 16
    for (int i = 0; i < CHUNK; i++) {
        const float d  = x_s[sbase + i];
        const float bf = (float)(((i < 32 ? (w0 >> i) : (w1 >> (i - 32))) & 1u));
        sn3 += bf;
        const float db = d * bf;
        sy = fmaf(db, db, sy);
        const float nd  = (sn3 == 0.0f) ? 1.0f : sn3;
        const float var = __fdividef(sy, nd);
        // std > 1e-5  <=>  var > 1e-10 ; else std := 1
        const float inv_std = (var > 1e-10f) ? rsqrtf(var) : 1.0f;
        float r = d * inv_std;
        r = fminf(100.0f, fmaxf(-100.0f, r));
        __stcs(og + gbase + (size_t)i * Cn, r);
    }
}

extern "C" void kernel_launch(void* const* d_in, const int* in_sizes, int n_in,
                              void* d_out, int out_size) {
    const float* x = (const float*)d_in[0];
    const float* m = (const float*)d_in[1];
    float*       o = (float*)d_out;

    void* fptr = nullptr;
    cudaGetSymbolAddress(&fptr, g_flags);
    cudaMemsetAsync(fptr, 0, sizeof(unsigned) * 2 * NCHAIN, 0);

    cudaFuncSetAttribute(crevin_kernel,
                         cudaFuncAttributeMaxDynamicSharedMemorySize, SMEM_BYTES);

    dim3 grid(LINKS, NCG, Bn);   // link fastest -> chain predecessors have lower bid
    crevin_kernel<<<grid, THREADS, SMEM_BYTES>>>(x, m, o);
}

// round 4
// speedup vs baseline: 2.4684x; 1.1177x over previous
#include <cuda_runtime.h>
#include <cstdint>

// CausalRevIN, B=16, T=8192, C=128, f32, C innermost.
// out = clip((x-mean)/std, -100, 100); mean = cumsum(x)/n, n = max(cumsum(1-mask),1);
// std = sqrt(cumsum(((x-mean)*(1-mask))^2)/n); std<=1e-5 -> 1.
//
// v3b: register-resident chunks (no SMEM data tile), parallel lookback
// (publish local segment totals immediately; sum predecessor totals in fixed
// order). Resubmission of v3 after infra failure; (sx,sn) packed as float2.

namespace {
constexpr int Bn = 16;
constexpr int Tn = 8192;
constexpr int Cn = 128;

constexpr int CS      = 32;            // channels per block (lane = channel)
constexpr int LINKS   = 16;            // T segments per chain
constexpr int TSEG    = Tn / LINKS;    // 512
constexpr int THREADS = 512;
constexpr int TPC     = THREADS / CS;  // 16 chunks per channel (warp = chunk)
constexpr int CHUNK   = TSEG / TPC;    // 32 timesteps -> one 32-bit mask word
constexpr int NCG     = Cn / CS;       // 4 channel groups

constexpr int NCHAIN  = Bn * NCG * LINKS;  // 1024
} // namespace

__device__ float2   g_sxn[NCHAIN * CS];    // packed (sum_x, sum_n)
__device__ float    g_sy [NCHAIN * CS];
__device__ unsigned g_flags[2 * NCHAIN];   // [A|B][chain]

__device__ __forceinline__ unsigned ld_acquire(const unsigned* p) {
    unsigned v;
    asm volatile("ld.acquire.gpu.global.u32 %0, [%1];" : "=r"(v) : "l"(p) : "memory");
    return v;
}
__device__ __forceinline__ void st_release(unsigned* p, unsigned v) {
    asm volatile("st.release.gpu.global.u32 [%0], %1;" :: "l"(p), "r"(v) : "memory");
}

__global__ __launch_bounds__(THREADS, 2)
void crevin_kernel(const float* __restrict__ xg,
                   const float* __restrict__ mg,
                   float* __restrict__ og)
{
    __shared__ float sc_x[THREADS];
    __shared__ float sc_n[THREADS];
    __shared__ float sc_y[THREADS];
    __shared__ float bxs[CS], bns[CS], bys[CS];

    const int tid  = threadIdx.x;
    const int c    = tid & 31;        // channel within group = lane
    const int j    = tid >> 5;        // chunk index = warp id (0..15)
    const int link = blockIdx.x;      // T segment (fastest-varying bid)
    const int cg   = blockIdx.y;
    const int b    = blockIdx.z;

    const size_t gbase = ((size_t)b * Tn + (size_t)link * TSEG + j * CHUNK) * Cn
                       + cg * CS + c;
    const float* xp = xg + gbase;
    const float* mp = mg + gbase;

    // ---- phase 0: load chunk into registers, fused sums + mask bits ----
    float xr[CHUNK];
    unsigned w = 0u;
    float cx = 0.0f;
#pragma unroll
    for (int i = 0; i < CHUNK; i++) {
        const float xv = __ldcs(xp + i * Cn);
        const float mv = __ldcs(mp + i * Cn);
        xr[i] = xv;
        cx += xv;
        if (mv == 0.0f) w |= (1u << i);        // 1 = observed
    }
    const float cn = (float)__popc(w);

    // ---- local exclusive scan over the 16 chunks of each channel ----
    sc_x[j * 32 + c] = cx;
    sc_n[j * 32 + c] = cn;
    __syncthreads();
    float px = 0.0f, pn = 0.0f;
    for (int k = 0; k < j; k++) {              // j warp-uniform
        px += sc_x[k * 32 + c];
        pn += sc_n[k * 32 + c];
    }

    const int chain = (b * NCG + cg) * LINKS + link;
    const int cb    = chain - link;            // first link of this chain

    // ---- publish local totals for lookback A (no dependence on preds) ----
    if (j == TPC - 1) {
        g_sxn[chain * CS + c] = make_float2(px + cx, pn + cn);
        __threadfence();
        __syncwarp();
        if (c == 0) st_release(&g_flags[chain], 1u);
    }

    // ---- lookback A: warp 0 waits for all preds, sums totals in order ----
    if (j == 0) {
        if (link > 0) {
            for (;;) {
                unsigned f = (c < link) ? ld_acquire(&g_flags[cb + c]) : 1u;
                if (__all_sync(0xffffffffu, f != 0u)) break;
            }
        }
        float bx = 0.0f, bn = 0.0f;
        for (int p = 0; p < link; p++) {
            const float2 v = *(const float2*)__builtin_assume_aligned(
                                 &g_sxn[(cb + p) * CS + c], 8);
            bx += v.x;
            bn += v.y;
        }
        bxs[c] = bx;
        bns[c] = bn;
    }
    __syncthreads();

    // ---- phase 2: running mean, d = x - mean (in regs), chunk sum of y ----
    float sx = bxs[c] + px;
    float sn = bns[c] + pn;
    float cy = 0.0f;
#pragma unroll
    for (int i = 0; i < CHUNK; i++) {
        const float xv = xr[i];
        const bool  ob = (w >> i) & 1u;
        sx += xv;
        if (ob) sn += 1.0f;
        const float nd   = (sn == 0.0f) ? 1.0f : sn;
        const float mean = __fdividef(sx, nd);
        const float d    = xv - mean;
        xr[i] = d;
        const float db = ob ? d : 0.0f;
        cy = fmaf(db, db, cy);
    }

    sc_y[j * 32 + c] = cy;
    __syncthreads();
    float py = 0.0f;
    for (int k = 0; k < j; k++) py += sc_y[k * 32 + c];

    // ---- publish local y totals; lookback B ----
    if (j == TPC - 1) {
        g_sy[chain * CS + c] = py + cy;
        __threadfence();
        __syncwarp();
        if (c == 0) st_release(&g_flags[NCHAIN + chain], 1u);
    }
    if (j == 0) {
        if (link > 0) {
            for (;;) {
                unsigned f = (c < link) ? ld_acquire(&g_flags[NCHAIN + cb + c]) : 1u;
                if (__all_sync(0xffffffffu, f != 0u)) break;
            }
        }
        float by = 0.0f;
        for (int p = 0; p < link; p++) by += __ldcg(&g_sy[(cb + p) * CS + c]);
        bys[c] = by;
    }
    __syncthreads();

    // ---- phase 3: running variance, normalize + clamp, coalesced store ----
    float sy  = bys[c] + py;
    float sn3 = bns[c] + pn;
    float* op = og + gbase;
#pragma unroll
    for (int i = 0; i < CHUNK; i++) {
        const float d  = xr[i];
        const bool  ob = (w >> i) & 1u;
        if (ob) sn3 += 1.0f;
        const float db = ob ? d : 0.0f;
        sy = fmaf(db, db, sy);
        const float nd  = (sn3 == 0.0f) ? 1.0f : sn3;
        const float var = __fdividef(sy, nd);
        // std > 1e-5  <=>  var > 1e-10 ; else std := 1
        const float inv_std = (var > 1e-10f) ? rsqrtf(var) : 1.0f;
        float r = d * inv_std;
        r = fminf(100.0f, fmaxf(-100.0f, r));
        __stcs(op + i * Cn, r);
    }
}

extern "C" void kernel_launch(void* const* d_in, const int* in_sizes, int n_in,
                              void* d_out, int out_size) {
    const float* x = (const float*)d_in[0];
    const float* m = (const float*)d_in[1];
    float*       o = (float*)d_out;

    static void* fptr = nullptr;
    if (!fptr) cudaGetSymbolAddress(&fptr, g_flags);
    cudaMemsetAsync(fptr, 0, sizeof(unsigned) * 2 * NCHAIN, 0);

    cudaFuncSetAttribute(crevin_kernel,
                         cudaFuncAttributeMaxDynamicSharedMemorySize, 0);

    dim3 grid(LINKS, NCG, Bn);   // link fastest -> chain members co-resident,
                                 // preds always at lower bid (deadlock-free)
    crevin_kernel<<<grid, THREADS>>>(x, m, o);
}